// round 2
// baseline (speedup 1.0000x reference)
#include <cuda_runtime.h>
#include <math.h>

// Problem constants
#define B_ 8
#define N_ 1024
#define E_ 128

// ---------------- scratch (static device globals; no allocation) ----------
__device__ float g_Hp[B_ * N_ * E_];            // 4 MB
__device__ float g_qkv[B_ * N_ * 3 * E_];       // 12 MB
__device__ float g_attn[(size_t)B_ * N_ * N_];  // 32 MB
__device__ float g_o[B_ * N_ * E_];             // 4 MB
__device__ float g_o2[B_ * N_ * E_];            // 4 MB

// ---------------------------------------------------------------------------
// Generic GEMM + bias:  C[M x NC] = A[M x 128] @ W[128 x NC] + bias
// Tiles: BM=64 rows, BN=128 cols, KT=32. 256 threads, 4x8 micro-tile.
// grid.x = M/64, grid.y = NC/128
// ---------------------------------------------------------------------------
__global__ __launch_bounds__(256) void gemm_bias(
    const float* __restrict__ A, const float* __restrict__ W,
    const float* __restrict__ bias, float* __restrict__ C, int NC)
{
    __shared__ float As[32][68];    // transposed A tile: As[k][row]
    __shared__ float Ws[32][132];   // W tile: Ws[k][col]

    int row0 = blockIdx.x * 64;
    int col0 = blockIdx.y * 128;
    int tid  = threadIdx.x;
    int tx   = tid & 15;       // col group
    int ty   = tid >> 4;       // row group

    float acc[4][8] = {};

    for (int k0 = 0; k0 < 128; k0 += 32) {
        // load A tile: 64 rows x 32 k = 512 float4
        #pragma unroll
        for (int i = 0; i < 2; i++) {
            int idx = tid + i * 256;
            int r   = idx >> 3;            // 8 float4 per row
            int kk  = (idx & 7) << 2;
            float4 v = *(const float4*)&A[(size_t)(row0 + r) * 128 + k0 + kk];
            As[kk + 0][r] = v.x; As[kk + 1][r] = v.y;
            As[kk + 2][r] = v.z; As[kk + 3][r] = v.w;
        }
        // load W tile: 32 k x 128 cols = 1024 float4
        #pragma unroll
        for (int i = 0; i < 4; i++) {
            int idx = tid + i * 256;
            int kk  = idx >> 5;
            int c   = (idx & 31) << 2;
            *(float4*)&Ws[kk][c] =
                *(const float4*)&W[(size_t)(k0 + kk) * NC + col0 + c];
        }
        __syncthreads();

        #pragma unroll
        for (int kk = 0; kk < 32; kk++) {
            float a[4], b[8];
            *(float4*)&a[0] = *(const float4*)&As[kk][ty * 4];
            *(float4*)&b[0] = *(const float4*)&Ws[kk][tx * 8];
            *(float4*)&b[4] = *(const float4*)&Ws[kk][tx * 8 + 4];
            #pragma unroll
            for (int i = 0; i < 4; i++)
                #pragma unroll
                for (int j = 0; j < 8; j++)
                    acc[i][j] = fmaf(a[i], b[j], acc[i][j]);
        }
        __syncthreads();
    }

    float bv[8];
    #pragma unroll
    for (int j = 0; j < 8; j++) bv[j] = bias[col0 + tx * 8 + j];

    #pragma unroll
    for (int i = 0; i < 4; i++) {
        size_t off = (size_t)(row0 + ty * 4 + i) * NC + col0 + tx * 8;
        float4 o0, o1;
        o0.x = acc[i][0] + bv[0]; o0.y = acc[i][1] + bv[1];
        o0.z = acc[i][2] + bv[2]; o0.w = acc[i][3] + bv[3];
        o1.x = acc[i][4] + bv[4]; o1.y = acc[i][5] + bv[5];
        o1.z = acc[i][6] + bv[6]; o1.w = acc[i][7] + bv[7];
        *(float4*)&C[off]     = o0;
        *(float4*)&C[off + 4] = o1;
    }
}

// ---------------------------------------------------------------------------
// Gated scores: out[b,n,m] = leakyrelu(dot(Hp[b,n], Hp[b,m])) * Adj[b,n,m]
// 128x128 tile per block, 256 threads, 8x8 micro. grid = (8, 8, 8)
// ---------------------------------------------------------------------------
__global__ __launch_bounds__(256) void gated_scores(
    const float* __restrict__ Hp, const float* __restrict__ Adj,
    float* __restrict__ out)
{
    __shared__ float Ns[32][132];
    __shared__ float Ms[32][132];

    int b  = blockIdx.z;
    int n0 = blockIdx.x * 128;
    int m0 = blockIdx.y * 128;
    const float* Hb = Hp + (size_t)b * N_ * E_;

    int tid = threadIdx.x;
    int tx  = tid & 15;
    int ty  = tid >> 4;

    float acc[8][8] = {};

    for (int k0 = 0; k0 < 128; k0 += 32) {
        #pragma unroll
        for (int i = 0; i < 4; i++) {
            int idx = tid + i * 256;     // 1024 float4 per tile
            int r   = idx >> 3;
            int kk  = (idx & 7) << 2;
            float4 v = *(const float4*)&Hb[(size_t)(n0 + r) * 128 + k0 + kk];
            Ns[kk + 0][r] = v.x; Ns[kk + 1][r] = v.y;
            Ns[kk + 2][r] = v.z; Ns[kk + 3][r] = v.w;
            float4 u = *(const float4*)&Hb[(size_t)(m0 + r) * 128 + k0 + kk];
            Ms[kk + 0][r] = u.x; Ms[kk + 1][r] = u.y;
            Ms[kk + 2][r] = u.z; Ms[kk + 3][r] = u.w;
        }
        __syncthreads();

        #pragma unroll
        for (int kk = 0; kk < 32; kk++) {
            float a[8], c[8];
            *(float4*)&a[0] = *(const float4*)&Ns[kk][ty * 8];
            *(float4*)&a[4] = *(const float4*)&Ns[kk][ty * 8 + 4];
            *(float4*)&c[0] = *(const float4*)&Ms[kk][tx * 8];
            *(float4*)&c[4] = *(const float4*)&Ms[kk][tx * 8 + 4];
            #pragma unroll
            for (int i = 0; i < 8; i++)
                #pragma unroll
                for (int j = 0; j < 8; j++)
                    acc[i][j] = fmaf(a[i], c[j], acc[i][j]);
        }
        __syncthreads();
    }

    #pragma unroll
    for (int i = 0; i < 8; i++) {
        size_t base = ((size_t)b * N_ + n0 + ty * 8 + i) * N_ + m0 + tx * 8;
        float4 a0 = *(const float4*)&Adj[base];
        float4 a1 = *(const float4*)&Adj[base + 4];
        float s[8];
        #pragma unroll
        for (int j = 0; j < 8; j++) {
            float v = acc[i][j];
            s[j] = (v >= 0.f) ? v : 0.2f * v;
        }
        float4 r0, r1;
        r0.x = s[0] * a0.x; r0.y = s[1] * a0.y;
        r0.z = s[2] * a0.z; r0.w = s[3] * a0.w;
        r1.x = s[4] * a1.x; r1.y = s[5] * a1.y;
        r1.z = s[6] * a1.z; r1.w = s[7] * a1.w;
        *(float4*)&out[base]     = r0;
        *(float4*)&out[base + 4] = r1;
    }
}

// ---------------------------------------------------------------------------
// In-place row softmax over last dim (1024). One block per row, 256 threads.
// ---------------------------------------------------------------------------
__global__ __launch_bounds__(256) void row_softmax(float* __restrict__ attn)
{
    __shared__ float red[16];
    size_t row = blockIdx.x;
    float4* p  = (float4*)(attn + row * N_);
    int tid    = threadIdx.x;

    float4 v = p[tid];
    float mx = fmaxf(fmaxf(v.x, v.y), fmaxf(v.z, v.w));
    #pragma unroll
    for (int o = 16; o > 0; o >>= 1)
        mx = fmaxf(mx, __shfl_xor_sync(0xffffffffu, mx, o));
    if ((tid & 31) == 0) red[tid >> 5] = mx;
    __syncthreads();
    float m2 = red[0];
    #pragma unroll
    for (int i = 1; i < 8; i++) m2 = fmaxf(m2, red[i]);

    v.x = __expf(v.x - m2); v.y = __expf(v.y - m2);
    v.z = __expf(v.z - m2); v.w = __expf(v.w - m2);
    float s = (v.x + v.y) + (v.z + v.w);
    #pragma unroll
    for (int o = 16; o > 0; o >>= 1)
        s += __shfl_xor_sync(0xffffffffu, s, o);
    if ((tid & 31) == 0) red[8 + (tid >> 5)] = s;
    __syncthreads();
    float tot = 0.f;
    #pragma unroll
    for (int i = 0; i < 8; i++) tot += red[8 + i];
    float r = 1.0f / tot;
    v.x *= r; v.y *= r; v.z *= r; v.w *= r;
    p[tid] = v;
}

// ---------------------------------------------------------------------------
// Fused multi-head attention.
// Block: 32 query rows x all 8 heads, 256 threads: thread = (h = t>>5, n = t&31).
// Warp == one head -> k/v smem reads are uniform broadcasts.
// scores = q.k/4 + attn_w (mask, shared across heads); softmax without max-sub
// (scores are O(1), mathematically identical); accumulate p*v.
// grid = (N/32, B)
// ---------------------------------------------------------------------------
__global__ __launch_bounds__(256, 2) void mha_kernel(
    const float* __restrict__ qkv, const float* __restrict__ attn,
    float* __restrict__ O)
{
    __shared__ float Ks[32][128];
    __shared__ float Vs[32][128];
    __shared__ float Ws[32][33];    // Ws[m][n], padded

    int b  = blockIdx.y;
    int n0 = blockIdx.x * 32;
    int t  = threadIdx.x;
    int h  = t >> 5;
    int nl = t & 31;

    const float* qp = qkv + ((size_t)(b * N_ + n0 + nl)) * 384 + h * 16;
    float q[16];
    #pragma unroll
    for (int d = 0; d < 16; d += 4) {
        float4 v = *(const float4*)&qp[d];
        q[d] = v.x * 0.25f; q[d + 1] = v.y * 0.25f;
        q[d + 2] = v.z * 0.25f; q[d + 3] = v.w * 0.25f;
    }

    float acc[16] = {};
    float l = 0.f;

    const float* kb = qkv + (size_t)b * N_ * 384;
    const float* wb = attn + ((size_t)b * N_ + n0) * N_;

    for (int m0 = 0; m0 < N_; m0 += 32) {
        // load K/V tiles: 32 rows x 128 floats each = 1024 float4 per array
        #pragma unroll
        for (int i = 0; i < 4; i++) {
            int idx = t + i * 256;
            int r   = idx >> 5;
            int c   = (idx & 31) << 2;
            const float* rowp = kb + (size_t)(m0 + r) * 384;
            *(float4*)&Ks[r][c] = *(const float4*)&rowp[128 + c];
            *(float4*)&Vs[r][c] = *(const float4*)&rowp[256 + c];
        }
        // load mask tile transposed: Ws[m][n]
        {
            int n  = t >> 3;
            int mq = (t & 7) << 2;
            float4 w = *(const float4*)&wb[(size_t)n * N_ + m0 + mq];
            Ws[mq + 0][n] = w.x; Ws[mq + 1][n] = w.y;
            Ws[mq + 2][n] = w.z; Ws[mq + 3][n] = w.w;
        }
        __syncthreads();

        #pragma unroll 2
        for (int m = 0; m < 32; m++) {
            float kv[16];
            *(float4*)&kv[0]  = *(const float4*)&Ks[m][h * 16];
            *(float4*)&kv[4]  = *(const float4*)&Ks[m][h * 16 + 4];
            *(float4*)&kv[8]  = *(const float4*)&Ks[m][h * 16 + 8];
            *(float4*)&kv[12] = *(const float4*)&Ks[m][h * 16 + 12];
            // 4 independent FMA chains for ILP
            float s0 = q[0] * kv[0], s1 = q[1] * kv[1];
            float s2 = q[2] * kv[2], s3 = q[3] * kv[3];
            #pragma unroll
            for (int d = 4; d < 16; d += 4) {
                s0 = fmaf(q[d + 0], kv[d + 0], s0);
                s1 = fmaf(q[d + 1], kv[d + 1], s1);
                s2 = fmaf(q[d + 2], kv[d + 2], s2);
                s3 = fmaf(q[d + 3], kv[d + 3], s3);
            }
            float s = Ws[m][nl] + ((s0 + s1) + (s2 + s3));
            float p = __expf(s);
            l += p;
            float vv[16];
            *(float4*)&vv[0]  = *(const float4*)&Vs[m][h * 16];
            *(float4*)&vv[4]  = *(const float4*)&Vs[m][h * 16 + 4];
            *(float4*)&vv[8]  = *(const float4*)&Vs[m][h * 16 + 8];
            *(float4*)&vv[12] = *(const float4*)&Vs[m][h * 16 + 12];
            #pragma unroll
            for (int d = 0; d < 16; d++)
                acc[d] = fmaf(p, vv[d], acc[d]);
        }
        __syncthreads();
    }

    float r = 1.0f / l;
    float* op = O + ((size_t)(b * N_ + n0 + nl)) * 128 + h * 16;
    #pragma unroll
    for (int d = 0; d < 16; d += 4) {
        float4 v;
        v.x = acc[d] * r; v.y = acc[d + 1] * r;
        v.z = acc[d + 2] * r; v.w = acc[d + 3] * r;
        *(float4*)&op[d] = v;
    }
}

// ---------------------------------------------------------------------------
extern "C" void kernel_launch(void* const* d_in, const int* in_sizes, int n_in,
                              void* d_out, int out_size)
{
    const float* H     = (const float*)d_in[0];
    const float* A     = (const float*)d_in[1];
    const float* W_lin = (const float*)d_in[2];
    const float* b_lin = (const float*)d_in[3];
    const float* W_in  = (const float*)d_in[4];
    const float* b_in  = (const float*)d_in[5];
    const float* W_out = (const float*)d_in[6];
    const float* b_out = (const float*)d_in[7];
    const float* W_fin = (const float*)d_in[8];
    const float* b_fin = (const float*)d_in[9];
    float* out = (float*)d_out;

    float *Hp, *qkvp, *attnp, *op, *o2p;
    cudaGetSymbolAddress((void**)&Hp,    g_Hp);
    cudaGetSymbolAddress((void**)&qkvp,  g_qkv);
    cudaGetSymbolAddress((void**)&attnp, g_attn);
    cudaGetSymbolAddress((void**)&op,    g_o);
    cudaGetSymbolAddress((void**)&o2p,   g_o2);

    // 1. Hp = H @ W_lin + b_lin               (8192 x 128)
    gemm_bias<<<dim3(128, 1), 256>>>(H, W_lin, b_lin, Hp, 128);
    // 2. qkv = Hp @ W_in + b_in               (8192 x 384)
    gemm_bias<<<dim3(128, 3), 256>>>(Hp, W_in, b_in, qkvp, 384);
    // 3. gated = leaky(Hp Hp^T) * A           (8 x 1024 x 1024)
    gated_scores<<<dim3(8, 8, 8), 256>>>(Hp, A, attnp);
    // 4. attn_w = softmax_rows(gated)
    row_softmax<<<B_ * N_, 256>>>(attnp);
    // 5. fused MHA -> o                       (8192 x 128)
    mha_kernel<<<dim3(32, 8), 256>>>(qkvp, attnp, op);
    // 6. o2 = o @ W_out + b_out
    gemm_bias<<<dim3(128, 1), 256>>>(op, W_out, b_out, o2p, 128);
    // 7. out = o2 @ W_fin + b_fin
    gemm_bias<<<dim3(128, 1), 256>>>(o2p, W_fin, b_fin, out, 128);
}

// round 4
// speedup vs baseline: 1.0434x; 1.0434x over previous
#include <cuda_runtime.h>
#include <math.h>
#include <stdint.h>

// Problem constants
#define B_ 8
#define N_ 1024
#define E_ 128

typedef unsigned long long ull;

// ---------------- packed f32x2 helpers (sm_103a FFMA2 path) ----------------
__device__ __forceinline__ ull bcast2(float a) {
    ull r; asm("mov.b64 %0, {%1, %1};" : "=l"(r) : "f"(a)); return r;
}
__device__ __forceinline__ void fma2(ull& d, ull a, ull b) {
    asm("fma.rn.f32x2 %0, %1, %2, %0;" : "+l"(d) : "l"(a), "l"(b));
}
__device__ __forceinline__ ull mul2(ull a, ull b) {
    ull d; asm("mul.rn.f32x2 %0, %1, %2;" : "=l"(d) : "l"(a), "l"(b)); return d;
}
__device__ __forceinline__ void unpack2(ull v, float& lo, float& hi) {
    asm("mov.b64 {%0, %1}, %2;" : "=f"(lo), "=f"(hi) : "l"(v));
}
// 128-bit shared load as two packed f32x2 operands
__device__ __forceinline__ void lds2x2(ull& a, ull& b, uint32_t addr) {
    asm volatile("ld.shared.v2.b64 {%0, %1}, [%2];"
                 : "=l"(a), "=l"(b) : "r"(addr));
}
__device__ __forceinline__ uint32_t saddr(const void* p) {
    return (uint32_t)__cvta_generic_to_shared(p);
}

// ---------------- scratch (static device globals; no allocation) ----------
__device__ float g_Hp[B_ * N_ * E_];            // 4 MB
__device__ float g_qkv[B_ * N_ * 3 * E_];       // 12 MB
__device__ float g_attn[(size_t)B_ * N_ * N_];  // 32 MB (unnormalized exp)
__device__ float g_rowsum[B_ * N_];             // 32 KB
__device__ float g_o[B_ * N_ * E_];             // 4 MB
__device__ float g_o2[B_ * N_ * E_];            // 4 MB

// ---------------------------------------------------------------------------
// Generic GEMM + bias:  C[M x NC] = A[M x 128] @ W[128 x NC] + bias
// BM=64, BN=128, KT=32. 256 threads, 4x8 micro-tile via FFMA2.
// ---------------------------------------------------------------------------
__global__ __launch_bounds__(256) void gemm_bias(
    const float* __restrict__ A, const float* __restrict__ W,
    const float* __restrict__ bias, float* __restrict__ C, int NC)
{
    __shared__ float As[32][68];    // transposed A tile: As[k][row]
    __shared__ float Ws[32][132];   // W tile: Ws[k][col]  (row stride 528B, 16B-aligned)

    int row0 = blockIdx.x * 64;
    int col0 = blockIdx.y * 128;
    int tid  = threadIdx.x;
    int tx   = tid & 15;       // col group (8 cols)
    int ty   = tid >> 4;       // row group (4 rows)

    ull acc2[4][4] = {};
    uint32_t wb = saddr(&Ws[0][tx * 8]);

    for (int k0 = 0; k0 < 128; k0 += 32) {
        #pragma unroll
        for (int i = 0; i < 2; i++) {
            int idx = tid + i * 256;
            int r   = idx >> 3;
            int kk  = (idx & 7) << 2;
            float4 v = *(const float4*)&A[(size_t)(row0 + r) * 128 + k0 + kk];
            As[kk + 0][r] = v.x; As[kk + 1][r] = v.y;
            As[kk + 2][r] = v.z; As[kk + 3][r] = v.w;
        }
        #pragma unroll
        for (int i = 0; i < 4; i++) {
            int idx = tid + i * 256;
            int kk  = idx >> 5;
            int c   = (idx & 31) << 2;
            *(float4*)&Ws[kk][c] =
                *(const float4*)&W[(size_t)(k0 + kk) * NC + col0 + c];
        }
        __syncthreads();

        #pragma unroll
        for (int kk = 0; kk < 32; kk++) {
            float a[4];
            *(float4*)&a[0] = *(const float4*)&As[kk][ty * 4];
            ull b2[4];
            lds2x2(b2[0], b2[1], wb + kk * 528);
            lds2x2(b2[2], b2[3], wb + kk * 528 + 16);
            #pragma unroll
            for (int i = 0; i < 4; i++) {
                ull av = bcast2(a[i]);
                #pragma unroll
                for (int j = 0; j < 4; j++) fma2(acc2[i][j], av, b2[j]);
            }
        }
        __syncthreads();
    }

    float bv[8];
    #pragma unroll
    for (int j = 0; j < 8; j++) bv[j] = bias[col0 + tx * 8 + j];

    #pragma unroll
    for (int i = 0; i < 4; i++) {
        float s[8];
        #pragma unroll
        for (int j = 0; j < 4; j++) unpack2(acc2[i][j], s[2 * j], s[2 * j + 1]);
        size_t off = (size_t)(row0 + ty * 4 + i) * NC + col0 + tx * 8;
        float4 o0, o1;
        o0.x = s[0] + bv[0]; o0.y = s[1] + bv[1];
        o0.z = s[2] + bv[2]; o0.w = s[3] + bv[3];
        o1.x = s[4] + bv[4]; o1.y = s[5] + bv[5];
        o1.z = s[6] + bv[6]; o1.w = s[7] + bv[7];
        *(float4*)&C[off]     = o0;
        *(float4*)&C[off + 4] = o1;
    }
}

// ---------------------------------------------------------------------------
// Gated scores, fused exp + row-sum:
//   e[b,n,m] = exp( leakyrelu(dot(Hp[b,n],Hp[b,m])) * Adj[b,n,m] )
//   rowsum[b,n] += partial sums (atomic, 8 partials per row)
// 128x128 tile per block, 256 threads, 8x8 micro via FFMA2. grid = (8,8,8)
// ---------------------------------------------------------------------------
__global__ __launch_bounds__(256) void gated_scores(
    const float* __restrict__ Hp, const float* __restrict__ Adj,
    float* __restrict__ out, float* __restrict__ rowsum)
{
    __shared__ float Ns[32][132];
    __shared__ float Ms[32][132];

    int b  = blockIdx.z;
    int n0 = blockIdx.x * 128;
    int m0 = blockIdx.y * 128;
    const float* Hb = Hp + (size_t)b * N_ * E_;

    int tid = threadIdx.x;
    int tx  = tid & 15;
    int ty  = tid >> 4;

    ull acc2[8][4] = {};
    uint32_t mb = saddr(&Ms[0][tx * 8]);

    for (int k0 = 0; k0 < 128; k0 += 32) {
        #pragma unroll
        for (int i = 0; i < 4; i++) {
            int idx = tid + i * 256;
            int r   = idx >> 3;
            int kk  = (idx & 7) << 2;
            float4 v = *(const float4*)&Hb[(size_t)(n0 + r) * 128 + k0 + kk];
            Ns[kk + 0][r] = v.x; Ns[kk + 1][r] = v.y;
            Ns[kk + 2][r] = v.z; Ns[kk + 3][r] = v.w;
            float4 u = *(const float4*)&Hb[(size_t)(m0 + r) * 128 + k0 + kk];
            Ms[kk + 0][r] = u.x; Ms[kk + 1][r] = u.y;
            Ms[kk + 2][r] = u.z; Ms[kk + 3][r] = u.w;
        }
        __syncthreads();

        #pragma unroll
        for (int kk = 0; kk < 32; kk++) {
            float a[8];
            *(float4*)&a[0] = *(const float4*)&Ns[kk][ty * 8];
            *(float4*)&a[4] = *(const float4*)&Ns[kk][ty * 8 + 4];
            ull c2[4];
            lds2x2(c2[0], c2[1], mb + kk * 528);
            lds2x2(c2[2], c2[3], mb + kk * 528 + 16);
            #pragma unroll
            for (int i = 0; i < 8; i++) {
                ull av = bcast2(a[i]);
                #pragma unroll
                for (int j = 0; j < 4; j++) fma2(acc2[i][j], av, c2[j]);
            }
        }
        __syncthreads();
    }

    #pragma unroll
    for (int i = 0; i < 8; i++) {
        int n = n0 + ty * 8 + i;
        size_t base = ((size_t)b * N_ + n) * N_ + m0 + tx * 8;
        float4 a0 = *(const float4*)&Adj[base];
        float4 a1 = *(const float4*)&Adj[base + 4];
        float s[8];
        #pragma unroll
        for (int j = 0; j < 4; j++) unpack2(acc2[i][j], s[2 * j], s[2 * j + 1]);
        float adj[8] = {a0.x, a0.y, a0.z, a0.w, a1.x, a1.y, a1.z, a1.w};
        float e[8];
        float rs = 0.f;
        #pragma unroll
        for (int j = 0; j < 8; j++) {
            float v = s[j];
            v = (v >= 0.f) ? v : 0.2f * v;
            e[j] = __expf(v * adj[j]);
            rs += e[j];
        }
        float4 r0, r1;
        r0.x = e[0]; r0.y = e[1]; r0.z = e[2]; r0.w = e[3];
        r1.x = e[4]; r1.y = e[5]; r1.z = e[6]; r1.w = e[7];
        *(float4*)&out[base]     = r0;
        *(float4*)&out[base + 4] = r1;
        // reduce rs over the 16 tx-lanes (stay within half-warp)
        #pragma unroll
        for (int o = 8; o > 0; o >>= 1)
            rs += __shfl_xor_sync(0xffffffffu, rs, o);
        if (tx == 0)
            atomicAdd(&rowsum[(size_t)b * N_ + n], rs);
    }
}

// ---------------------------------------------------------------------------
// Fused multi-head attention (mask = unnormalized exp * inv_rowsum).
// Block: 32 query rows x 8 heads = 256 threads; warp == one head.
// FFMA2 packed inner loops; softmax without max-sub (scores O(1)).
// grid = (N/32, B)
// ---------------------------------------------------------------------------
__global__ __launch_bounds__(256, 2) void mha_kernel(
    const float* __restrict__ qkv, const float* __restrict__ attn,
    const float* __restrict__ rowsum, float* __restrict__ O)
{
    __shared__ float Ks[32][128];
    __shared__ float Vs[32][128];
    __shared__ float Ws[32][33];    // Ws[m][n], padded

    int b  = blockIdx.y;
    int n0 = blockIdx.x * 32;
    int t  = threadIdx.x;
    int h  = t >> 5;
    int nl = t & 31;

    const float* qp = qkv + ((size_t)(b * N_ + n0 + nl)) * 384 + h * 16;
    float q[16];
    #pragma unroll
    for (int d = 0; d < 16; d += 4) {
        float4 v = *(const float4*)&qp[d];
        q[d] = v.x * 0.25f; q[d + 1] = v.y * 0.25f;
        q[d + 2] = v.z * 0.25f; q[d + 3] = v.w * 0.25f;
    }
    ull q2[8];
    #pragma unroll
    for (int d = 0; d < 8; d++) {
        ull r; asm("mov.b64 %0, {%1, %2};" : "=l"(r) : "f"(q[2 * d]), "f"(q[2 * d + 1]));
        q2[d] = r;
    }

    float invs = 1.0f / rowsum[(size_t)b * N_ + n0 + nl];

    ull acc2[8] = {};
    float l = 0.f;

    const float* kb = qkv + (size_t)b * N_ * 384;
    const float* wb = attn + ((size_t)b * N_ + n0) * N_;

    uint32_t ksb = saddr(&Ks[0][h * 16]);
    uint32_t vsb = saddr(&Vs[0][h * 16]);

    for (int m0 = 0; m0 < N_; m0 += 32) {
        #pragma unroll
        for (int i = 0; i < 4; i++) {
            int idx = t + i * 256;
            int r   = idx >> 5;
            int c   = (idx & 31) << 2;
            const float* rowp = kb + (size_t)(m0 + r) * 384;
            *(float4*)&Ks[r][c] = *(const float4*)&rowp[128 + c];
            *(float4*)&Vs[r][c] = *(const float4*)&rowp[256 + c];
        }
        {
            int n  = t >> 3;
            int mq = (t & 7) << 2;
            float4 w = *(const float4*)&wb[(size_t)n * N_ + m0 + mq];
            Ws[mq + 0][n] = w.x; Ws[mq + 1][n] = w.y;
            Ws[mq + 2][n] = w.z; Ws[mq + 3][n] = w.w;
        }
        __syncthreads();

        #pragma unroll 4
        for (int m = 0; m < 32; m++) {
            uint32_t ka = ksb + m * 512;
            ull k2[8];
            lds2x2(k2[0], k2[1], ka);
            lds2x2(k2[2], k2[3], ka + 16);
            lds2x2(k2[4], k2[5], ka + 32);
            lds2x2(k2[6], k2[7], ka + 48);
            ull sa = mul2(q2[0], k2[0]);
            ull sb = mul2(q2[1], k2[1]);
            fma2(sa, q2[2], k2[2]); fma2(sb, q2[3], k2[3]);
            fma2(sa, q2[4], k2[4]); fma2(sb, q2[5], k2[5]);
            fma2(sa, q2[6], k2[6]); fma2(sb, q2[7], k2[7]);
            float alo, ahi, blo, bhi;
            unpack2(sa, alo, ahi); unpack2(sb, blo, bhi);
            float dot = (alo + ahi) + (blo + bhi);
            float s = fmaf(Ws[m][nl], invs, dot);
            float p = __expf(s);
            l += p;
            ull p2 = bcast2(p);
            uint32_t va = vsb + m * 512;
            ull v2[8];
            lds2x2(v2[0], v2[1], va);
            lds2x2(v2[2], v2[3], va + 16);
            lds2x2(v2[4], v2[5], va + 32);
            lds2x2(v2[6], v2[7], va + 48);
            #pragma unroll
            for (int d = 0; d < 8; d++) fma2(acc2[d], p2, v2[d]);
        }
        __syncthreads();
    }

    float r = 1.0f / l;
    float* op = O + ((size_t)(b * N_ + n0 + nl)) * 128 + h * 16;
    float a[16];
    #pragma unroll
    for (int d = 0; d < 8; d++) unpack2(acc2[d], a[2 * d], a[2 * d + 1]);
    #pragma unroll
    for (int d = 0; d < 16; d += 4) {
        float4 v;
        v.x = a[d] * r; v.y = a[d + 1] * r;
        v.z = a[d + 2] * r; v.w = a[d + 3] * r;
        *(float4*)&op[d] = v;
    }
}

// ---------------------------------------------------------------------------
extern "C" void kernel_launch(void* const* d_in, const int* in_sizes, int n_in,
                              void* d_out, int out_size)
{
    const float* H     = (const float*)d_in[0];
    const float* A     = (const float*)d_in[1];
    const float* W_lin = (const float*)d_in[2];
    const float* b_lin = (const float*)d_in[3];
    const float* W_in  = (const float*)d_in[4];
    const float* b_in  = (const float*)d_in[5];
    const float* W_out = (const float*)d_in[6];
    const float* b_out = (const float*)d_in[7];
    const float* W_fin = (const float*)d_in[8];
    const float* b_fin = (const float*)d_in[9];
    float* out = (float*)d_out;

    float *Hp, *qkvp, *attnp, *rowsump, *op, *o2p;
    cudaGetSymbolAddress((void**)&Hp,      g_Hp);
    cudaGetSymbolAddress((void**)&qkvp,    g_qkv);
    cudaGetSymbolAddress((void**)&attnp,   g_attn);
    cudaGetSymbolAddress((void**)&rowsump, g_rowsum);
    cudaGetSymbolAddress((void**)&op,      g_o);
    cudaGetSymbolAddress((void**)&o2p,     g_o2);

    // 1. Hp = H @ W_lin + b_lin               (8192 x 128)
    gemm_bias<<<dim3(128, 1), 256>>>(H, W_lin, b_lin, Hp, 128);
    // 2. qkv = Hp @ W_in + b_in               (8192 x 384)
    gemm_bias<<<dim3(128, 3), 256>>>(Hp, W_in, b_in, qkvp, 384);
    // 3. rowsum = 0
    cudaMemsetAsync(rowsump, 0, B_ * N_ * sizeof(float));
    // 4. e = exp(leaky(Hp Hp^T) * A), rowsum += partials
    gated_scores<<<dim3(8, 8, 8), 256>>>(Hp, A, attnp, rowsump);
    // 5. fused MHA -> o                       (8192 x 128)
    mha_kernel<<<dim3(32, 8), 256>>>(qkvp, attnp, rowsump, op);
    // 6. o2 = o @ W_out + b_out
    gemm_bias<<<dim3(128, 1), 256>>>(op, W_out, b_out, o2p, 128);
    // 7. out = o2 @ W_fin + b_fin
    gemm_bias<<<dim3(128, 1), 256>>>(o2p, W_fin, b_fin, out, 128);
}

// round 5
// speedup vs baseline: 1.0757x; 1.0310x over previous
#include <cuda_runtime.h>
#include <math.h>
#include <stdint.h>

// Problem constants
#define B_ 8
#define N_ 1024
#define E_ 128

typedef unsigned long long ull;

// ---------------- packed f32x2 helpers (sm_103a FFMA2 path) ----------------
__device__ __forceinline__ ull bcast2(float a) {
    ull r; asm("mov.b64 %0, {%1, %1};" : "=l"(r) : "f"(a)); return r;
}
__device__ __forceinline__ ull pack2(float lo, float hi) {
    ull r; asm("mov.b64 %0, {%1, %2};" : "=l"(r) : "f"(lo), "f"(hi)); return r;
}
__device__ __forceinline__ void fma2(ull& d, ull a, ull b) {
    asm("fma.rn.f32x2 %0, %1, %2, %0;" : "+l"(d) : "l"(a), "l"(b));
}
__device__ __forceinline__ ull mul2(ull a, ull b) {
    ull d; asm("mul.rn.f32x2 %0, %1, %2;" : "=l"(d) : "l"(a), "l"(b)); return d;
}
__device__ __forceinline__ void unpack2(ull v, float& lo, float& hi) {
    asm("mov.b64 {%0, %1}, %2;" : "=f"(lo), "=f"(hi) : "l"(v));
}
// 128-bit shared load as two packed f32x2 operands
__device__ __forceinline__ void lds2x2(ull& a, ull& b, uint32_t addr) {
    asm volatile("ld.shared.v2.b64 {%0, %1}, [%2];"
                 : "=l"(a), "=l"(b) : "r"(addr));
}
__device__ __forceinline__ uint32_t saddr(const void* p) {
    return (uint32_t)__cvta_generic_to_shared(p);
}

// ---------------- scratch (static device globals; no allocation) ----------
__device__ float g_Hp[B_ * N_ * E_];            // 4 MB
__device__ float g_qkv[B_ * N_ * 3 * E_];       // 12 MB
__device__ float g_attn[(size_t)B_ * N_ * N_];  // 32 MB (unnormalized exp)
__device__ float g_rowsum[B_ * N_];             // 32 KB
__device__ float g_oA[B_ * N_ * E_];            // 4 MB (split-K partial 0)
__device__ float g_oB[B_ * N_ * E_];            // 4 MB (split-K partial 1)
__device__ float g_lA[B_ * N_ * 8];             // 256 KB
__device__ float g_lB[B_ * N_ * 8];
__device__ float g_o[B_ * N_ * E_];             // combined MHA output
__device__ float g_o2[B_ * N_ * E_];            // out-proj output

// ---------------------------------------------------------------------------
// Generic GEMM + bias:  C[M x NC] = A[M x 128] @ W[128 x NC] + bias
// BM=64, BN=128, KT=32. 256 threads, 4x8 micro-tile via FFMA2.
// ---------------------------------------------------------------------------
__global__ __launch_bounds__(256) void gemm_bias(
    const float* __restrict__ A, const float* __restrict__ W,
    const float* __restrict__ bias, float* __restrict__ C, int NC)
{
    __shared__ float As[32][68];
    __shared__ float Ws[32][132];

    int row0 = blockIdx.x * 64;
    int col0 = blockIdx.y * 128;
    int tid  = threadIdx.x;
    int tx   = tid & 15;
    int ty   = tid >> 4;

    ull acc2[4][4] = {};
    uint32_t wb = saddr(&Ws[0][tx * 8]);

    for (int k0 = 0; k0 < 128; k0 += 32) {
        #pragma unroll
        for (int i = 0; i < 2; i++) {
            int idx = tid + i * 256;
            int r   = idx >> 3;
            int kk  = (idx & 7) << 2;
            float4 v = *(const float4*)&A[(size_t)(row0 + r) * 128 + k0 + kk];
            As[kk + 0][r] = v.x; As[kk + 1][r] = v.y;
            As[kk + 2][r] = v.z; As[kk + 3][r] = v.w;
        }
        #pragma unroll
        for (int i = 0; i < 4; i++) {
            int idx = tid + i * 256;
            int kk  = idx >> 5;
            int c   = (idx & 31) << 2;
            *(float4*)&Ws[kk][c] =
                *(const float4*)&W[(size_t)(k0 + kk) * NC + col0 + c];
        }
        __syncthreads();

        #pragma unroll
        for (int kk = 0; kk < 32; kk++) {
            float a[4];
            *(float4*)&a[0] = *(const float4*)&As[kk][ty * 4];
            ull b2[4];
            lds2x2(b2[0], b2[1], wb + kk * 528);
            lds2x2(b2[2], b2[3], wb + kk * 528 + 16);
            #pragma unroll
            for (int i = 0; i < 4; i++) {
                ull av = bcast2(a[i]);
                #pragma unroll
                for (int j = 0; j < 4; j++) fma2(acc2[i][j], av, b2[j]);
            }
        }
        __syncthreads();
    }

    float bv[8];
    #pragma unroll
    for (int j = 0; j < 8; j++) bv[j] = bias[col0 + tx * 8 + j];

    #pragma unroll
    for (int i = 0; i < 4; i++) {
        float s[8];
        #pragma unroll
        for (int j = 0; j < 4; j++) unpack2(acc2[i][j], s[2 * j], s[2 * j + 1]);
        size_t off = (size_t)(row0 + ty * 4 + i) * NC + col0 + tx * 8;
        float4 o0, o1;
        o0.x = s[0] + bv[0]; o0.y = s[1] + bv[1];
        o0.z = s[2] + bv[2]; o0.w = s[3] + bv[3];
        o1.x = s[4] + bv[4]; o1.y = s[5] + bv[5];
        o1.z = s[6] + bv[6]; o1.w = s[7] + bv[7];
        *(float4*)&C[off]     = o0;
        *(float4*)&C[off + 4] = o1;
    }
}

// ---------------------------------------------------------------------------
// Gated scores, fused exp + row-sum:
//   e[b,n,m] = exp( leakyrelu(dot(Hp[b,n],Hp[b,m])) * Adj[b,n,m] )
//   rowsum[b,n] += partial sums (atomic, 8 partials per row)
// ---------------------------------------------------------------------------
__global__ __launch_bounds__(256) void gated_scores(
    const float* __restrict__ Hp, const float* __restrict__ Adj,
    float* __restrict__ out, float* __restrict__ rowsum)
{
    __shared__ float Ns[32][132];
    __shared__ float Ms[32][132];

    int b  = blockIdx.z;
    int n0 = blockIdx.x * 128;
    int m0 = blockIdx.y * 128;
    const float* Hb = Hp + (size_t)b * N_ * E_;

    int tid = threadIdx.x;
    int tx  = tid & 15;
    int ty  = tid >> 4;

    ull acc2[8][4] = {};
    uint32_t mb = saddr(&Ms[0][tx * 8]);

    for (int k0 = 0; k0 < 128; k0 += 32) {
        #pragma unroll
        for (int i = 0; i < 4; i++) {
            int idx = tid + i * 256;
            int r   = idx >> 3;
            int kk  = (idx & 7) << 2;
            float4 v = *(const float4*)&Hb[(size_t)(n0 + r) * 128 + k0 + kk];
            Ns[kk + 0][r] = v.x; Ns[kk + 1][r] = v.y;
            Ns[kk + 2][r] = v.z; Ns[kk + 3][r] = v.w;
            float4 u = *(const float4*)&Hb[(size_t)(m0 + r) * 128 + k0 + kk];
            Ms[kk + 0][r] = u.x; Ms[kk + 1][r] = u.y;
            Ms[kk + 2][r] = u.z; Ms[kk + 3][r] = u.w;
        }
        __syncthreads();

        #pragma unroll
        for (int kk = 0; kk < 32; kk++) {
            float a[8];
            *(float4*)&a[0] = *(const float4*)&Ns[kk][ty * 8];
            *(float4*)&a[4] = *(const float4*)&Ns[kk][ty * 8 + 4];
            ull c2[4];
            lds2x2(c2[0], c2[1], mb + kk * 528);
            lds2x2(c2[2], c2[3], mb + kk * 528 + 16);
            #pragma unroll
            for (int i = 0; i < 8; i++) {
                ull av = bcast2(a[i]);
                #pragma unroll
                for (int j = 0; j < 4; j++) fma2(acc2[i][j], av, c2[j]);
            }
        }
        __syncthreads();
    }

    #pragma unroll
    for (int i = 0; i < 8; i++) {
        int n = n0 + ty * 8 + i;
        size_t base = ((size_t)b * N_ + n) * N_ + m0 + tx * 8;
        float4 a0 = *(const float4*)&Adj[base];
        float4 a1 = *(const float4*)&Adj[base + 4];
        float s[8];
        #pragma unroll
        for (int j = 0; j < 4; j++) unpack2(acc2[i][j], s[2 * j], s[2 * j + 1]);
        float adj[8] = {a0.x, a0.y, a0.z, a0.w, a1.x, a1.y, a1.z, a1.w};
        float e[8];
        float rs = 0.f;
        #pragma unroll
        for (int j = 0; j < 8; j++) {
            float v = s[j];
            v = (v >= 0.f) ? v : 0.2f * v;
            e[j] = __expf(v * adj[j]);
            rs += e[j];
        }
        float4 r0, r1;
        r0.x = e[0]; r0.y = e[1]; r0.z = e[2]; r0.w = e[3];
        r1.x = e[4]; r1.y = e[5]; r1.z = e[6]; r1.w = e[7];
        *(float4*)&out[base]     = r0;
        *(float4*)&out[base + 4] = r1;
        #pragma unroll
        for (int o = 8; o > 0; o >>= 1)
            rs += __shfl_xor_sync(0xffffffffu, rs, o);
        if (tx == 0)
            atomicAdd(&rowsum[(size_t)b * N_ + n], rs);
    }
}

// ---------------------------------------------------------------------------
// Fused MHA, split-K over keys, 2 queries per thread.
// Block: 256 threads; warp = head h; each lane covers queries (n0+nl, n0+32+nl).
// Processes keys [z*512, z*512+512). Writes UNNORMALIZED partial acc + l.
// grid = (N/64, B, 2)
// ---------------------------------------------------------------------------
__global__ __launch_bounds__(256, 2) void mha_split(
    const float* __restrict__ qkv, const float* __restrict__ attn,
    const float* __restrict__ rowsum,
    float* __restrict__ OA, float* __restrict__ OB,
    float* __restrict__ LA, float* __restrict__ LB)
{
    __shared__ float Ks[32][128];
    __shared__ float Vs[32][128];
    __shared__ float Ws[32][65];    // Ws[m][n_local], n_local in [0,64)

    int b   = blockIdx.y;
    int n0  = blockIdx.x * 64;
    int ms0 = blockIdx.z * 512;
    int t   = threadIdx.x;
    int h   = t >> 5;
    int nl  = t & 31;
    int na  = n0 + nl;
    int nb  = n0 + 32 + nl;

    float* Op = blockIdx.z ? OB : OA;
    float* Lp = blockIdx.z ? LB : LA;

    // load + scale queries
    ull q2a[8], q2b[8];
    {
        const float* qa = qkv + ((size_t)(b * N_ + na)) * 384 + h * 16;
        const float* qb = qkv + ((size_t)(b * N_ + nb)) * 384 + h * 16;
        #pragma unroll
        for (int d = 0; d < 16; d += 4) {
            float4 v = *(const float4*)&qa[d];
            q2a[d / 2]     = pack2(v.x * 0.25f, v.y * 0.25f);
            q2a[d / 2 + 1] = pack2(v.z * 0.25f, v.w * 0.25f);
            float4 u = *(const float4*)&qb[d];
            q2b[d / 2]     = pack2(u.x * 0.25f, u.y * 0.25f);
            q2b[d / 2 + 1] = pack2(u.z * 0.25f, u.w * 0.25f);
        }
    }
    float invsa = 1.0f / rowsum[(size_t)b * N_ + na];
    float invsb = 1.0f / rowsum[(size_t)b * N_ + nb];

    ull acca[8] = {}, accb[8] = {};
    float la = 0.f, lb = 0.f;

    const float* kb = qkv + (size_t)b * N_ * 384;
    const float* wb = attn + ((size_t)b * N_ + n0) * N_;

    uint32_t ksb = saddr(&Ks[0][h * 16]);
    uint32_t vsb = saddr(&Vs[0][h * 16]);

    for (int m0 = ms0; m0 < ms0 + 512; m0 += 32) {
        // K/V tiles: 32 rows x 128 floats each
        #pragma unroll
        for (int i = 0; i < 4; i++) {
            int idx = t + i * 256;
            int r   = idx >> 5;
            int c   = (idx & 31) << 2;
            const float* rowp = kb + (size_t)(m0 + r) * 384;
            *(float4*)&Ks[r][c] = *(const float4*)&rowp[128 + c];
            *(float4*)&Vs[r][c] = *(const float4*)&rowp[256 + c];
        }
        // mask tile transposed: Ws[m][n_local], 64 n x 32 m
        #pragma unroll
        for (int i = 0; i < 2; i++) {
            int idx = t + i * 256;
            int n   = idx >> 3;
            int mq  = (idx & 7) << 2;
            float4 w = *(const float4*)&wb[(size_t)n * N_ + m0 + mq];
            Ws[mq + 0][n] = w.x; Ws[mq + 1][n] = w.y;
            Ws[mq + 2][n] = w.z; Ws[mq + 3][n] = w.w;
        }
        __syncthreads();

        #pragma unroll 4
        for (int m = 0; m < 32; m++) {
            uint32_t ka = ksb + m * 512;
            ull k2[8];
            lds2x2(k2[0], k2[1], ka);
            lds2x2(k2[2], k2[3], ka + 16);
            lds2x2(k2[4], k2[5], ka + 32);
            lds2x2(k2[6], k2[7], ka + 48);
            ull sa0 = mul2(q2a[0], k2[0]);
            ull sa1 = mul2(q2a[1], k2[1]);
            ull sb0 = mul2(q2b[0], k2[0]);
            ull sb1 = mul2(q2b[1], k2[1]);
            #pragma unroll
            for (int d = 2; d < 8; d += 2) {
                fma2(sa0, q2a[d],     k2[d]);
                fma2(sa1, q2a[d + 1], k2[d + 1]);
                fma2(sb0, q2b[d],     k2[d]);
                fma2(sb1, q2b[d + 1], k2[d + 1]);
            }
            float a0, a1, a2, a3, b0, b1, b2, b3;
            unpack2(sa0, a0, a1); unpack2(sa1, a2, a3);
            unpack2(sb0, b0, b1); unpack2(sb1, b2, b3);
            float dota = (a0 + a1) + (a2 + a3);
            float dotb = (b0 + b1) + (b2 + b3);
            float pa = __expf(fmaf(Ws[m][nl],      invsa, dota));
            float pb = __expf(fmaf(Ws[m][nl + 32], invsb, dotb));
            la += pa; lb += pb;
            ull pa2 = bcast2(pa), pb2 = bcast2(pb);
            uint32_t va = vsb + m * 512;
            ull v2[8];
            lds2x2(v2[0], v2[1], va);
            lds2x2(v2[2], v2[3], va + 16);
            lds2x2(v2[4], v2[5], va + 32);
            lds2x2(v2[6], v2[7], va + 48);
            #pragma unroll
            for (int d = 0; d < 8; d++) {
                fma2(acca[d], pa2, v2[d]);
                fma2(accb[d], pb2, v2[d]);
            }
        }
        __syncthreads();
    }

    // write unnormalized partials
    {
        float* oa = Op + ((size_t)(b * N_ + na)) * 128 + h * 16;
        float* ob = Op + ((size_t)(b * N_ + nb)) * 128 + h * 16;
        float s[16];
        #pragma unroll
        for (int d = 0; d < 8; d++) unpack2(acca[d], s[2 * d], s[2 * d + 1]);
        #pragma unroll
        for (int d = 0; d < 16; d += 4)
            *(float4*)&oa[d] = make_float4(s[d], s[d + 1], s[d + 2], s[d + 3]);
        #pragma unroll
        for (int d = 0; d < 8; d++) unpack2(accb[d], s[2 * d], s[2 * d + 1]);
        #pragma unroll
        for (int d = 0; d < 16; d += 4)
            *(float4*)&ob[d] = make_float4(s[d], s[d + 1], s[d + 2], s[d + 3]);
        Lp[((size_t)(b * N_ + na)) * 8 + h] = la;
        Lp[((size_t)(b * N_ + nb)) * 8 + h] = lb;
    }
}

// ---------------------------------------------------------------------------
// Combine split-K partials: O = (OA + OB) / (LA + LB)
// ---------------------------------------------------------------------------
__global__ __launch_bounds__(256) void combine_kernel(
    const float* __restrict__ OA, const float* __restrict__ OB,
    const float* __restrict__ LA, const float* __restrict__ LB,
    float* __restrict__ O)
{
    int f = blockIdx.x * 256 + threadIdx.x;   // float4 index
    int e = f << 2;
    int row = e >> 7;                          // b*N + n
    int h   = (e & 127) >> 4;
    float inv = 1.0f / (LA[(size_t)row * 8 + h] + LB[(size_t)row * 8 + h]);
    float4 a = ((const float4*)OA)[f];
    float4 b = ((const float4*)OB)[f];
    float4 o;
    o.x = (a.x + b.x) * inv; o.y = (a.y + b.y) * inv;
    o.z = (a.z + b.z) * inv; o.w = (a.w + b.w) * inv;
    ((float4*)O)[f] = o;
}

// ---------------------------------------------------------------------------
extern "C" void kernel_launch(void* const* d_in, const int* in_sizes, int n_in,
                              void* d_out, int out_size)
{
    const float* H     = (const float*)d_in[0];
    const float* A     = (const float*)d_in[1];
    const float* W_lin = (const float*)d_in[2];
    const float* b_lin = (const float*)d_in[3];
    const float* W_in  = (const float*)d_in[4];
    const float* b_in  = (const float*)d_in[5];
    const float* W_out = (const float*)d_in[6];
    const float* b_out = (const float*)d_in[7];
    const float* W_fin = (const float*)d_in[8];
    const float* b_fin = (const float*)d_in[9];
    float* out = (float*)d_out;

    float *Hp, *qkvp, *attnp, *rowsump, *oAp, *oBp, *lAp, *lBp, *op, *o2p;
    cudaGetSymbolAddress((void**)&Hp,      g_Hp);
    cudaGetSymbolAddress((void**)&qkvp,    g_qkv);
    cudaGetSymbolAddress((void**)&attnp,   g_attn);
    cudaGetSymbolAddress((void**)&rowsump, g_rowsum);
    cudaGetSymbolAddress((void**)&oAp,     g_oA);
    cudaGetSymbolAddress((void**)&oBp,     g_oB);
    cudaGetSymbolAddress((void**)&lAp,     g_lA);
    cudaGetSymbolAddress((void**)&lBp,     g_lB);
    cudaGetSymbolAddress((void**)&op,      g_o);
    cudaGetSymbolAddress((void**)&o2p,     g_o2);

    // 1. Hp = H @ W_lin + b_lin               (8192 x 128)
    gemm_bias<<<dim3(128, 1), 256>>>(H, W_lin, b_lin, Hp, 128);
    // 2. qkv = Hp @ W_in + b_in               (8192 x 384)
    gemm_bias<<<dim3(128, 3), 256>>>(Hp, W_in, b_in, qkvp, 384);
    // 3. rowsum = 0
    cudaMemsetAsync(rowsump, 0, B_ * N_ * sizeof(float));
    // 4. e = exp(leaky(Hp Hp^T) * A), rowsum += partials
    gated_scores<<<dim3(8, 8, 8), 256>>>(Hp, A, attnp, rowsump);
    // 5. fused MHA split-K -> partials
    mha_split<<<dim3(16, 8, 2), 256>>>(qkvp, attnp, rowsump, oAp, oBp, lAp, lBp);
    // 6. combine partials -> o
    combine_kernel<<<B_ * N_ * E_ / (4 * 256), 256>>>(oAp, oBp, lAp, lBp, op);
    // 7. o2 = o @ W_out + b_out
    gemm_bias<<<dim3(128, 1), 256>>>(op, W_out, b_out, o2p, 128);
    // 8. out = o2 @ W_fin + b_fin
    gemm_bias<<<dim3(128, 1), 256>>>(o2p, W_fin, b_fin, out, 128);
}

// round 6
// speedup vs baseline: 1.1815x; 1.0983x over previous
#include <cuda_runtime.h>
#include <math.h>
#include <stdint.h>

// Problem constants
#define B_ 8
#define N_ 1024
#define E_ 128

typedef unsigned long long ull;

// ---------------- packed f32x2 helpers (sm_103a FFMA2 path) ----------------
__device__ __forceinline__ ull bcast2(float a) {
    ull r; asm("mov.b64 %0, {%1, %1};" : "=l"(r) : "f"(a)); return r;
}
__device__ __forceinline__ void fma2(ull& d, ull a, ull b) {
    asm("fma.rn.f32x2 %0, %1, %2, %0;" : "+l"(d) : "l"(a), "l"(b));
}
__device__ __forceinline__ void unpack2(ull v, float& lo, float& hi) {
    asm("mov.b64 {%0, %1}, %2;" : "=f"(lo), "=f"(hi) : "l"(v));
}
__device__ __forceinline__ void lds2x2(ull& a, ull& b, uint32_t addr) {
    asm volatile("ld.shared.v2.b64 {%0, %1}, [%2];"
                 : "=l"(a), "=l"(b) : "r"(addr));
}
__device__ __forceinline__ uint32_t saddr(const void* p) {
    return (uint32_t)__cvta_generic_to_shared(p);
}

// ---------------- tf32 mma helpers ----------------------------------------
__device__ __forceinline__ float f2tf32(float x) {
    uint32_t r; asm("cvt.rna.tf32.f32 %0, %1;" : "=r"(r) : "f"(x));
    return __uint_as_float(r);
}
__device__ __forceinline__ void mma_tf32(float* d, const uint32_t* a,
                                         const uint32_t* b) {
    asm volatile(
        "mma.sync.aligned.m16n8k8.row.col.f32.tf32.tf32.f32 "
        "{%0,%1,%2,%3}, {%4,%5,%6,%7}, {%8,%9}, {%0,%1,%2,%3};\n"
        : "+f"(d[0]), "+f"(d[1]), "+f"(d[2]), "+f"(d[3])
        : "r"(a[0]), "r"(a[1]), "r"(a[2]), "r"(a[3]), "r"(b[0]), "r"(b[1]));
}

// ---------------- scratch (static device globals; no allocation) ----------
__device__ float g_Hp[B_ * N_ * E_];            // 4 MB
__device__ float g_qkv[B_ * N_ * 3 * E_];       // 12 MB
__device__ float g_attn[(size_t)B_ * N_ * N_];  // 32 MB (unnormalized exp)
__device__ float g_rowsum[B_ * N_];             // 32 KB
__device__ float g_o[B_ * N_ * E_];             // MHA output
__device__ float g_o2[B_ * N_ * E_];            // out-proj output

// ---------------------------------------------------------------------------
// Generic GEMM + bias:  C[M x NC] = A[M x 128] @ W[128 x NC] + bias
// ---------------------------------------------------------------------------
__global__ __launch_bounds__(256) void gemm_bias(
    const float* __restrict__ A, const float* __restrict__ W,
    const float* __restrict__ bias, float* __restrict__ C, int NC)
{
    __shared__ float As[32][68];
    __shared__ float Ws[32][132];

    int row0 = blockIdx.x * 64;
    int col0 = blockIdx.y * 128;
    int tid  = threadIdx.x;
    int tx   = tid & 15;
    int ty   = tid >> 4;

    ull acc2[4][4] = {};
    uint32_t wb = saddr(&Ws[0][tx * 8]);

    for (int k0 = 0; k0 < 128; k0 += 32) {
        #pragma unroll
        for (int i = 0; i < 2; i++) {
            int idx = tid + i * 256;
            int r   = idx >> 3;
            int kk  = (idx & 7) << 2;
            float4 v = *(const float4*)&A[(size_t)(row0 + r) * 128 + k0 + kk];
            As[kk + 0][r] = v.x; As[kk + 1][r] = v.y;
            As[kk + 2][r] = v.z; As[kk + 3][r] = v.w;
        }
        #pragma unroll
        for (int i = 0; i < 4; i++) {
            int idx = tid + i * 256;
            int kk  = idx >> 5;
            int c   = (idx & 31) << 2;
            *(float4*)&Ws[kk][c] =
                *(const float4*)&W[(size_t)(k0 + kk) * NC + col0 + c];
        }
        __syncthreads();

        #pragma unroll
        for (int kk = 0; kk < 32; kk++) {
            float a[4];
            *(float4*)&a[0] = *(const float4*)&As[kk][ty * 4];
            ull b2[4];
            lds2x2(b2[0], b2[1], wb + kk * 528);
            lds2x2(b2[2], b2[3], wb + kk * 528 + 16);
            #pragma unroll
            for (int i = 0; i < 4; i++) {
                ull av = bcast2(a[i]);
                #pragma unroll
                for (int j = 0; j < 4; j++) fma2(acc2[i][j], av, b2[j]);
            }
        }
        __syncthreads();
    }

    float bv[8];
    #pragma unroll
    for (int j = 0; j < 8; j++) bv[j] = bias[col0 + tx * 8 + j];

    #pragma unroll
    for (int i = 0; i < 4; i++) {
        float s[8];
        #pragma unroll
        for (int j = 0; j < 4; j++) unpack2(acc2[i][j], s[2 * j], s[2 * j + 1]);
        size_t off = (size_t)(row0 + ty * 4 + i) * NC + col0 + tx * 8;
        float4 o0, o1;
        o0.x = s[0] + bv[0]; o0.y = s[1] + bv[1];
        o0.z = s[2] + bv[2]; o0.w = s[3] + bv[3];
        o1.x = s[4] + bv[4]; o1.y = s[5] + bv[5];
        o1.z = s[6] + bv[6]; o1.w = s[7] + bv[7];
        *(float4*)&C[off]     = o0;
        *(float4*)&C[off + 4] = o1;
    }
}

// ---------------------------------------------------------------------------
// Gated scores, fused exp + row-sum (scalar FFMA2 — tensorize next round)
// ---------------------------------------------------------------------------
__global__ __launch_bounds__(256) void gated_scores(
    const float* __restrict__ Hp, const float* __restrict__ Adj,
    float* __restrict__ out, float* __restrict__ rowsum)
{
    __shared__ float Ns[32][132];
    __shared__ float Ms[32][132];

    int b  = blockIdx.z;
    int n0 = blockIdx.x * 128;
    int m0 = blockIdx.y * 128;
    const float* Hb = Hp + (size_t)b * N_ * E_;

    int tid = threadIdx.x;
    int tx  = tid & 15;
    int ty  = tid >> 4;

    ull acc2[8][4] = {};
    uint32_t mb = saddr(&Ms[0][tx * 8]);

    for (int k0 = 0; k0 < 128; k0 += 32) {
        #pragma unroll
        for (int i = 0; i < 4; i++) {
            int idx = tid + i * 256;
            int r   = idx >> 3;
            int kk  = (idx & 7) << 2;
            float4 v = *(const float4*)&Hb[(size_t)(n0 + r) * 128 + k0 + kk];
            Ns[kk + 0][r] = v.x; Ns[kk + 1][r] = v.y;
            Ns[kk + 2][r] = v.z; Ns[kk + 3][r] = v.w;
            float4 u = *(const float4*)&Hb[(size_t)(m0 + r) * 128 + k0 + kk];
            Ms[kk + 0][r] = u.x; Ms[kk + 1][r] = u.y;
            Ms[kk + 2][r] = u.z; Ms[kk + 3][r] = u.w;
        }
        __syncthreads();

        #pragma unroll
        for (int kk = 0; kk < 32; kk++) {
            float a[8];
            *(float4*)&a[0] = *(const float4*)&Ns[kk][ty * 8];
            *(float4*)&a[4] = *(const float4*)&Ns[kk][ty * 8 + 4];
            ull c2[4];
            lds2x2(c2[0], c2[1], mb + kk * 528);
            lds2x2(c2[2], c2[3], mb + kk * 528 + 16);
            #pragma unroll
            for (int i = 0; i < 8; i++) {
                ull av = bcast2(a[i]);
                #pragma unroll
                for (int j = 0; j < 4; j++) fma2(acc2[i][j], av, c2[j]);
            }
        }
        __syncthreads();
    }

    #pragma unroll
    for (int i = 0; i < 8; i++) {
        int n = n0 + ty * 8 + i;
        size_t base = ((size_t)b * N_ + n) * N_ + m0 + tx * 8;
        float4 a0 = *(const float4*)&Adj[base];
        float4 a1 = *(const float4*)&Adj[base + 4];
        float s[8];
        #pragma unroll
        for (int j = 0; j < 4; j++) unpack2(acc2[i][j], s[2 * j], s[2 * j + 1]);
        float adj[8] = {a0.x, a0.y, a0.z, a0.w, a1.x, a1.y, a1.z, a1.w};
        float e[8];
        float rs = 0.f;
        #pragma unroll
        for (int j = 0; j < 8; j++) {
            float v = s[j];
            v = (v >= 0.f) ? v : 0.2f * v;
            e[j] = __expf(v * adj[j]);
            rs += e[j];
        }
        float4 r0, r1;
        r0.x = e[0]; r0.y = e[1]; r0.z = e[2]; r0.w = e[3];
        r1.x = e[4]; r1.y = e[5]; r1.z = e[6]; r1.w = e[7];
        *(float4*)&out[base]     = r0;
        *(float4*)&out[base + 4] = r1;
        #pragma unroll
        for (int o = 8; o > 0; o >>= 1)
            rs += __shfl_xor_sync(0xffffffffu, rs, o);
        if (tx == 0)
            atomicAdd(&rowsum[(size_t)b * N_ + n], rs);
    }
}

// ---------------------------------------------------------------------------
// Tensor-core (tf32 mma.sync) fused MHA.
// Block = 32 queries x 8 heads (warp = head), loops all keys in 32-key tiles.
// grid = (N/32, B). Mask pre-scaled by 1/rowsum at staging.
// ---------------------------------------------------------------------------
struct MhaSmem {
    float Ks[32][132];      // K tile (tf32 bits), pad132: frag banks 4g+tig
    float Vs[32][132];      // V tile (tf32 bits)
    float Wm[32][36];       // mask tile, pre-scaled by invS
    float Ps[8][32][36];    // per-warp P tile (tf32 bits)
    float invS[32];
};

__global__ void __launch_bounds__(256, 2) mha_tc(
    const float* __restrict__ qkv, const float* __restrict__ attn,
    const float* __restrict__ rowsum, float* __restrict__ O)
{
    extern __shared__ char smem_raw[];
    MhaSmem& S = *reinterpret_cast<MhaSmem*>(smem_raw);

    int b    = blockIdx.y;
    int n0   = blockIdx.x * 32;
    int t    = threadIdx.x;
    int h    = t >> 5;
    int lane = t & 31;
    int g    = lane >> 2;   // group (row within fragment)
    int tig  = lane & 3;    // thread-in-group

    if (t < 32) S.invS[t] = 1.0f / rowsum[(size_t)b * N_ + n0 + t];

    // --- Q fragments in registers (scaled by 1/sqrt(16)=0.25, tf32) -------
    uint32_t qf[2][2][4];   // [m-tile i][k-step s][4]
    {
        const float* qbase = qkv + ((size_t)b * N_ + n0) * 384 + h * 16;
        #pragma unroll
        for (int i = 0; i < 2; i++)
            #pragma unroll
            for (int s = 0; s < 2; s++) {
                const float* p0 = qbase + (size_t)(16 * i + g) * 384 + 8 * s + tig;
                const float* p1 = p0 + 8 * 384;
                qf[i][s][0] = __float_as_uint(f2tf32(p0[0] * 0.25f));
                qf[i][s][1] = __float_as_uint(f2tf32(p1[0] * 0.25f));
                qf[i][s][2] = __float_as_uint(f2tf32(p0[4] * 0.25f));
                qf[i][s][3] = __float_as_uint(f2tf32(p1[4] * 0.25f));
            }
    }

    float oacc[2][2][4] = {};        // [m-tile][d-tile][4]
    float lsum[4] = {0.f, 0.f, 0.f, 0.f};

    const float* kvbase = qkv + (size_t)b * N_ * 384;
    const float* mbase  = attn + ((size_t)b * N_ + n0) * N_;

    int srow = t >> 3;            // 0..31 (stage row)
    int scol = (t & 7) * 16;      // K/V: 16 floats per thread
    int mcol = (t & 7) * 4;       // mask: 4 floats per thread

    for (int m0 = 0; m0 < N_; m0 += 32) {
        __syncthreads();   // prev compute done (also orders invS on iter 0)

        // ---- stage K, V (cvt to tf32), mask (pre-scaled) -----------------
        {
            const float* kr = kvbase + (size_t)(m0 + srow) * 384 + 128 + scol;
            const float* vr = kr + 128;
            #pragma unroll
            for (int c = 0; c < 16; c += 4) {
                float4 kx = *(const float4*)(kr + c);
                float4 vx = *(const float4*)(vr + c);
                *(float2*)&S.Ks[srow][scol + c] =
                    make_float2(f2tf32(kx.x), f2tf32(kx.y));
                *(float2*)&S.Ks[srow][scol + c + 2] =
                    make_float2(f2tf32(kx.z), f2tf32(kx.w));
                *(float2*)&S.Vs[srow][scol + c] =
                    make_float2(f2tf32(vx.x), f2tf32(vx.y));
                *(float2*)&S.Vs[srow][scol + c + 2] =
                    make_float2(f2tf32(vx.z), f2tf32(vx.w));
            }
            float4 w = *(const float4*)(mbase + (size_t)srow * N_ + m0 + mcol);
            float iv = S.invS[srow];
            *(float2*)&S.Wm[srow][mcol]     = make_float2(w.x * iv, w.y * iv);
            *(float2*)&S.Wm[srow][mcol + 2] = make_float2(w.z * iv, w.w * iv);
        }
        __syncthreads();

        // ---- QK^T: S[32q x 32k] = Q Ks^T ---------------------------------
        float sacc[2][4][4];
        #pragma unroll
        for (int i = 0; i < 2; i++)
            #pragma unroll
            for (int j = 0; j < 4; j++)
                #pragma unroll
                for (int e = 0; e < 4; e++) sacc[i][j][e] = 0.f;

        #pragma unroll
        for (int s = 0; s < 2; s++) {
            #pragma unroll
            for (int j = 0; j < 4; j++) {
                uint32_t bf[2];
                bf[0] = __float_as_uint(S.Ks[8 * j + g][h * 16 + 8 * s + tig]);
                bf[1] = __float_as_uint(S.Ks[8 * j + g][h * 16 + 8 * s + tig + 4]);
                mma_tf32(sacc[0][j], qf[0][s], bf);
                mma_tf32(sacc[1][j], qf[1][s], bf);
            }
        }

        // ---- epilogue: p = exp(s + mask*invS); accumulate l; P -> smem ---
        #pragma unroll
        for (int i = 0; i < 2; i++) {
            #pragma unroll
            for (int j = 0; j < 4; j++) {
                int r0 = 16 * i + g;
                int c  = 8 * j + 2 * tig;
                float2 w0 = *(const float2*)&S.Wm[r0][c];
                float2 w1 = *(const float2*)&S.Wm[r0 + 8][c];
                float p0 = __expf(sacc[i][j][0] + w0.x);
                float p1 = __expf(sacc[i][j][1] + w0.y);
                float p2 = __expf(sacc[i][j][2] + w1.x);
                float p3 = __expf(sacc[i][j][3] + w1.y);
                lsum[2 * i]     += p0 + p1;
                lsum[2 * i + 1] += p2 + p3;
                *(float2*)&S.Ps[h][r0][c] =
                    make_float2(f2tf32(p0), f2tf32(p1));
                *(float2*)&S.Ps[h][r0 + 8][c] =
                    make_float2(f2tf32(p2), f2tf32(p3));
            }
        }
        __syncwarp();

        // ---- PV: O[32q x 16d] += P Vs ------------------------------------
        #pragma unroll
        for (int kt = 0; kt < 4; kt++) {
            uint32_t bv[2][2];
            #pragma unroll
            for (int jd = 0; jd < 2; jd++) {
                bv[jd][0] = __float_as_uint(
                    S.Vs[8 * kt + tig][h * 16 + 8 * jd + g]);
                bv[jd][1] = __float_as_uint(
                    S.Vs[8 * kt + tig + 4][h * 16 + 8 * jd + g]);
            }
            uint32_t af[2][4];
            #pragma unroll
            for (int i = 0; i < 2; i++) {
                af[i][0] = __float_as_uint(S.Ps[h][16 * i + g][8 * kt + tig]);
                af[i][1] = __float_as_uint(S.Ps[h][16 * i + 8 + g][8 * kt + tig]);
                af[i][2] = __float_as_uint(S.Ps[h][16 * i + g][8 * kt + tig + 4]);
                af[i][3] = __float_as_uint(S.Ps[h][16 * i + 8 + g][8 * kt + tig + 4]);
            }
            #pragma unroll
            for (int i = 0; i < 2; i++)
                #pragma unroll
                for (int jd = 0; jd < 2; jd++)
                    mma_tf32(oacc[i][jd], af[i], bv[jd]);
        }
    }

    // ---- finalize: reduce l over quad, normalize, write ------------------
    #pragma unroll
    for (int k = 0; k < 4; k++) {
        lsum[k] += __shfl_xor_sync(0xffffffffu, lsum[k], 1);
        lsum[k] += __shfl_xor_sync(0xffffffffu, lsum[k], 2);
    }
    #pragma unroll
    for (int i = 0; i < 2; i++) {
        float r0inv = 1.0f / lsum[2 * i];
        float r1inv = 1.0f / lsum[2 * i + 1];
        #pragma unroll
        for (int jd = 0; jd < 2; jd++) {
            size_t base0 = ((size_t)b * N_ + n0 + 16 * i + g) * 128
                           + h * 16 + 8 * jd + 2 * tig;
            size_t base1 = base0 + (size_t)8 * 128;
            *(float2*)&O[base0] = make_float2(oacc[i][jd][0] * r0inv,
                                              oacc[i][jd][1] * r0inv);
            *(float2*)&O[base1] = make_float2(oacc[i][jd][2] * r1inv,
                                              oacc[i][jd][3] * r1inv);
        }
    }
}

// ---------------------------------------------------------------------------
extern "C" void kernel_launch(void* const* d_in, const int* in_sizes, int n_in,
                              void* d_out, int out_size)
{
    const float* H     = (const float*)d_in[0];
    const float* A     = (const float*)d_in[1];
    const float* W_lin = (const float*)d_in[2];
    const float* b_lin = (const float*)d_in[3];
    const float* W_in  = (const float*)d_in[4];
    const float* b_in  = (const float*)d_in[5];
    const float* W_out = (const float*)d_in[6];
    const float* b_out = (const float*)d_in[7];
    const float* W_fin = (const float*)d_in[8];
    const float* b_fin = (const float*)d_in[9];
    float* out = (float*)d_out;

    float *Hp, *qkvp, *attnp, *rowsump, *op, *o2p;
    cudaGetSymbolAddress((void**)&Hp,      g_Hp);
    cudaGetSymbolAddress((void**)&qkvp,    g_qkv);
    cudaGetSymbolAddress((void**)&attnp,   g_attn);
    cudaGetSymbolAddress((void**)&rowsump, g_rowsum);
    cudaGetSymbolAddress((void**)&op,      g_o);
    cudaGetSymbolAddress((void**)&o2p,     g_o2);

    static int smem_set = 0;
    if (!smem_set) {
        cudaFuncSetAttribute(mha_tc, cudaFuncAttributeMaxDynamicSharedMemorySize,
                             (int)sizeof(MhaSmem));
        smem_set = 1;
    }

    // 1. Hp = H @ W_lin + b_lin               (8192 x 128)
    gemm_bias<<<dim3(128, 1), 256>>>(H, W_lin, b_lin, Hp, 128);
    // 2. qkv = Hp @ W_in + b_in               (8192 x 384)
    gemm_bias<<<dim3(128, 3), 256>>>(Hp, W_in, b_in, qkvp, 384);
    // 3. rowsum = 0
    cudaMemsetAsync(rowsump, 0, B_ * N_ * sizeof(float));
    // 4. e = exp(leaky(Hp Hp^T) * A), rowsum += partials
    gated_scores<<<dim3(8, 8, 8), 256>>>(Hp, A, attnp, rowsump);
    // 5. tensor-core fused MHA -> o
    mha_tc<<<dim3(32, 8), 256, sizeof(MhaSmem)>>>(qkvp, attnp, rowsump, op);
    // 6. o2 = o @ W_out + b_out
    gemm_bias<<<dim3(128, 1), 256>>>(op, W_out, b_out, o2p, 128);
    // 7. out = o2 @ W_fin + b_fin
    gemm_bias<<<dim3(128, 1), 256>>>(o2p, W_fin, b_fin, out, 128);
}

// round 8
// speedup vs baseline: 1.4840x; 1.2561x over previous
#include <cuda_runtime.h>
#include <math.h>
#include <stdint.h>

// Problem constants
#define B_ 8
#define N_ 1024
#define E_ 128

typedef unsigned long long ull;

// ---------------- packed f32x2 helpers (sm_103a FFMA2 path) ----------------
__device__ __forceinline__ ull bcast2(float a) {
    ull r; asm("mov.b64 %0, {%1, %1};" : "=l"(r) : "f"(a)); return r;
}
__device__ __forceinline__ void fma2(ull& d, ull a, ull b) {
    asm("fma.rn.f32x2 %0, %1, %2, %0;" : "+l"(d) : "l"(a), "l"(b));
}
__device__ __forceinline__ void unpack2(ull v, float& lo, float& hi) {
    asm("mov.b64 {%0, %1}, %2;" : "=f"(lo), "=f"(hi) : "l"(v));
}
__device__ __forceinline__ void lds2x2(ull& a, ull& b, uint32_t addr) {
    asm volatile("ld.shared.v2.b64 {%0, %1}, [%2];"
                 : "=l"(a), "=l"(b) : "r"(addr));
}
__device__ __forceinline__ uint32_t saddr(const void* p) {
    return (uint32_t)__cvta_generic_to_shared(p);
}

// ---------------- tf32 mma helpers ----------------------------------------
__device__ __forceinline__ float f2tf32(float x) {
    uint32_t r; asm("cvt.rna.tf32.f32 %0, %1;" : "=r"(r) : "f"(x));
    return __uint_as_float(r);
}
__device__ __forceinline__ void mma_tf32(float* d, const uint32_t* a,
                                         const uint32_t* b) {
    asm volatile(
        "mma.sync.aligned.m16n8k8.row.col.f32.tf32.tf32.f32 "
        "{%0,%1,%2,%3}, {%4,%5,%6,%7}, {%8,%9}, {%0,%1,%2,%3};\n"
        : "+f"(d[0]), "+f"(d[1]), "+f"(d[2]), "+f"(d[3])
        : "r"(a[0]), "r"(a[1]), "r"(a[2]), "r"(a[3]), "r"(b[0]), "r"(b[1]));
}

// ---------------- cp.async helpers -----------------------------------------
__device__ __forceinline__ void cpa16(uint32_t dst, const void* src) {
    asm volatile("cp.async.cg.shared.global [%0], [%1], 16;"
                 :: "r"(dst), "l"(src));
}
__device__ __forceinline__ void cp_commit() {
    asm volatile("cp.async.commit_group;");
}
__device__ __forceinline__ void cp_wait1() {
    asm volatile("cp.async.wait_group 1;");
}
__device__ __forceinline__ void cp_wait0() {
    asm volatile("cp.async.wait_group 0;");
}

// ---------------- scratch (static device globals; no allocation) ----------
__device__ float g_Hp[B_ * N_ * E_];            // 4 MB
__device__ float g_qkv[B_ * N_ * 3 * E_];       // 12 MB
__device__ float g_attn[(size_t)B_ * N_ * N_];  // 32 MB (unnormalized exp)
__device__ float g_rowsum[B_ * N_];             // 32 KB
__device__ float g_o[B_ * N_ * E_];             // MHA output
__device__ float g_o2[B_ * N_ * E_];            // out-proj output

// ---------------------------------------------------------------------------
// Generic GEMM + bias:  C[M x NC] = A[M x 128] @ W[128 x NC] + bias
// ---------------------------------------------------------------------------
__global__ __launch_bounds__(256) void gemm_bias(
    const float* __restrict__ A, const float* __restrict__ W,
    const float* __restrict__ bias, float* __restrict__ C, int NC)
{
    __shared__ float As[32][68];
    __shared__ float Ws[32][132];

    int row0 = blockIdx.x * 64;
    int col0 = blockIdx.y * 128;
    int tid  = threadIdx.x;
    int tx   = tid & 15;
    int ty   = tid >> 4;

    ull acc2[4][4] = {};
    uint32_t wb = saddr(&Ws[0][tx * 8]);

    for (int k0 = 0; k0 < 128; k0 += 32) {
        #pragma unroll
        for (int i = 0; i < 2; i++) {
            int idx = tid + i * 256;
            int r   = idx >> 3;
            int kk  = (idx & 7) << 2;
            float4 v = *(const float4*)&A[(size_t)(row0 + r) * 128 + k0 + kk];
            As[kk + 0][r] = v.x; As[kk + 1][r] = v.y;
            As[kk + 2][r] = v.z; As[kk + 3][r] = v.w;
        }
        #pragma unroll
        for (int i = 0; i < 4; i++) {
            int idx = tid + i * 256;
            int kk  = idx >> 5;
            int c   = (idx & 31) << 2;
            *(float4*)&Ws[kk][c] =
                *(const float4*)&W[(size_t)(k0 + kk) * NC + col0 + c];
        }
        __syncthreads();

        #pragma unroll
        for (int kk = 0; kk < 32; kk++) {
            float a[4];
            *(float4*)&a[0] = *(const float4*)&As[kk][ty * 4];
            ull b2[4];
            lds2x2(b2[0], b2[1], wb + kk * 528);
            lds2x2(b2[2], b2[3], wb + kk * 528 + 16);
            #pragma unroll
            for (int i = 0; i < 4; i++) {
                ull av = bcast2(a[i]);
                #pragma unroll
                for (int j = 0; j < 4; j++) fma2(acc2[i][j], av, b2[j]);
            }
        }
        __syncthreads();
    }

    float bv[8];
    #pragma unroll
    for (int j = 0; j < 8; j++) bv[j] = bias[col0 + tx * 8 + j];

    #pragma unroll
    for (int i = 0; i < 4; i++) {
        float s[8];
        #pragma unroll
        for (int j = 0; j < 4; j++) unpack2(acc2[i][j], s[2 * j], s[2 * j + 1]);
        size_t off = (size_t)(row0 + ty * 4 + i) * NC + col0 + tx * 8;
        float4 o0, o1;
        o0.x = s[0] + bv[0]; o0.y = s[1] + bv[1];
        o0.z = s[2] + bv[2]; o0.w = s[3] + bv[3];
        o1.x = s[4] + bv[4]; o1.y = s[5] + bv[5];
        o1.z = s[6] + bv[6]; o1.w = s[7] + bv[7];
        *(float4*)&C[off]     = o0;
        *(float4*)&C[off + 4] = o1;
    }
}

// ---------------------------------------------------------------------------
// Tensor-core gated scores + fused exp + row-sum.
// Block tile 128(n) x 64(m); 8 warps = 2(n) x 4(m); each warp 64n x 16m.
// grid = (8, 16, 8). tf32 mma, rna cvt at staging.
// ---------------------------------------------------------------------------
__global__ __launch_bounds__(256) void gated_tc(
    const float* __restrict__ Hp, const float* __restrict__ Adj,
    float* __restrict__ out, float* __restrict__ rowsum)
{
    __shared__ float Ns[128][36];
    __shared__ float Ms[64][36];

    int b  = blockIdx.z;
    int n0 = blockIdx.x * 128;
    int m0 = blockIdx.y * 64;
    const float* Hb = Hp + (size_t)b * N_ * E_;

    int t    = threadIdx.x;
    int w    = t >> 5;
    int lane = t & 31;
    int g    = lane >> 2;
    int tig  = lane & 3;
    int wn   = (w & 1) * 64;     // n-offset within block tile
    int wm   = (w >> 1) * 16;    // m-offset within block tile

    float acc[4][2][4] = {};     // [mt (16 n-rows)][nt (8 m-cols)][4]

    for (int k0 = 0; k0 < 128; k0 += 32) {
        __syncthreads();
        // stage Ns: 128 rows x 32 k (tf32 rna)
        #pragma unroll
        for (int i = 0; i < 4; i++) {
            int idx = t + i * 256;
            int r = idx >> 3, kk = (idx & 7) << 2;
            float4 v = *(const float4*)&Hb[(size_t)(n0 + r) * 128 + k0 + kk];
            v.x = f2tf32(v.x); v.y = f2tf32(v.y);
            v.z = f2tf32(v.z); v.w = f2tf32(v.w);
            *(float4*)&Ns[r][kk] = v;
        }
        // stage Ms: 64 rows x 32 k
        #pragma unroll
        for (int i = 0; i < 2; i++) {
            int idx = t + i * 256;
            int r = idx >> 3, kk = (idx & 7) << 2;
            float4 v = *(const float4*)&Hb[(size_t)(m0 + r) * 128 + k0 + kk];
            v.x = f2tf32(v.x); v.y = f2tf32(v.y);
            v.z = f2tf32(v.z); v.w = f2tf32(v.w);
            *(float4*)&Ms[r][kk] = v;
        }
        __syncthreads();

        #pragma unroll
        for (int s = 0; s < 4; s++) {
            uint32_t af[4][4], bf[2][2];
            #pragma unroll
            for (int mt = 0; mt < 4; mt++) {
                const float* base = &Ns[wn + 16 * mt + g][8 * s + tig];
                af[mt][0] = __float_as_uint(base[0]);
                af[mt][1] = __float_as_uint(base[8 * 36]);
                af[mt][2] = __float_as_uint(base[4]);
                af[mt][3] = __float_as_uint(base[8 * 36 + 4]);
            }
            #pragma unroll
            for (int nt = 0; nt < 2; nt++) {
                const float* base = &Ms[wm + 8 * nt + g][8 * s + tig];
                bf[nt][0] = __float_as_uint(base[0]);
                bf[nt][1] = __float_as_uint(base[4]);
            }
            #pragma unroll
            for (int mt = 0; mt < 4; mt++)
                #pragma unroll
                for (int nt = 0; nt < 2; nt++)
                    mma_tf32(acc[mt][nt], af[mt], bf[nt]);
        }
    }

    // epilogue: leaky -> *Adj -> exp -> store + rowsum atomics
    #pragma unroll
    for (int mt = 0; mt < 4; mt++) {
        #pragma unroll
        for (int eh = 0; eh < 2; eh++) {
            int n = n0 + wn + 16 * mt + g + eh * 8;
            float partial = 0.f;
            #pragma unroll
            for (int nt = 0; nt < 2; nt++) {
                int m = m0 + wm + 8 * nt + 2 * tig;
                size_t addr = ((size_t)b * N_ + n) * N_ + m;
                float2 adj = *(const float2*)&Adj[addr];
                float v0 = acc[mt][nt][2 * eh];
                float v1 = acc[mt][nt][2 * eh + 1];
                v0 = (v0 >= 0.f) ? v0 : 0.2f * v0;
                v1 = (v1 >= 0.f) ? v1 : 0.2f * v1;
                float e0 = __expf(v0 * adj.x);
                float e1 = __expf(v1 * adj.y);
                partial += e0 + e1;
                *(float2*)&out[addr] = make_float2(e0, e1);
            }
            partial += __shfl_xor_sync(0xffffffffu, partial, 1);
            partial += __shfl_xor_sync(0xffffffffu, partial, 2);
            if (tig == 0)
                atomicAdd(&rowsum[(size_t)b * N_ + n], partial);
        }
    }
}

// ---------------------------------------------------------------------------
// Tensor-core fused MHA with cp.async double-buffered K/V/mask staging.
// Block = 32 queries x 8 heads (warp = head); grid = (N/32, B).
// K/V read raw fp32 (HW truncates to tf32); Q and P use rna cvt.
// ---------------------------------------------------------------------------
struct MhaSmem {
    float Ks[2][32][132];   // K tiles, pad132 -> frag banks 4g+tig
    float Vs[2][32][132];   // V tiles
    float Wm[2][32][36];    // mask tiles (raw, scaled by invS in epilogue)
    float Ps[8][32][36];    // per-warp P tile
};

__device__ __forceinline__ void mha_issue(
    MhaSmem& S, int bi, const float* kvbase, const float* mbase,
    int m0, int t)
{
    int srow = t >> 3;
    int sc16 = (t & 7) * 16;
    int mc4  = (t & 7) * 4;
    const float* kr = kvbase + (size_t)(m0 + srow) * 384 + 128 + sc16;
    uint32_t kd = saddr(&S.Ks[bi][srow][sc16]);
    uint32_t vd = saddr(&S.Vs[bi][srow][sc16]);
    #pragma unroll
    for (int c = 0; c < 16; c += 4) {
        cpa16(kd + c * 4, kr + c);
        cpa16(vd + c * 4, kr + 128 + c);
    }
    cpa16(saddr(&S.Wm[bi][srow][mc4]),
          mbase + (size_t)srow * N_ + m0 + mc4);
}

__global__ void __launch_bounds__(256, 2) mha_tc(
    const float* __restrict__ qkv, const float* __restrict__ attn,
    const float* __restrict__ rowsum, float* __restrict__ O)
{
    extern __shared__ char smem_raw[];
    MhaSmem& S = *reinterpret_cast<MhaSmem*>(smem_raw);

    int b    = blockIdx.y;
    int n0   = blockIdx.x * 32;
    int t    = threadIdx.x;
    int h    = t >> 5;
    int lane = t & 31;
    int g    = lane >> 2;
    int tig  = lane & 3;

    const float* kvbase = qkv + (size_t)b * N_ * 384;
    const float* mbase  = attn + ((size_t)b * N_ + n0) * N_;

    // prefetch first two key tiles
    mha_issue(S, 0, kvbase, mbase, 0, t);  cp_commit();
    mha_issue(S, 1, kvbase, mbase, 32, t); cp_commit();

    // per-thread 1/rowsum for the query rows this thread's fragments touch
    const float* rsb = rowsum + (size_t)b * N_ + n0;
    float is0 = 1.0f / rsb[g];
    float is1 = 1.0f / rsb[g + 8];
    float is2 = 1.0f / rsb[g + 16];
    float is3 = 1.0f / rsb[g + 24];

    // Q fragments in registers (scaled by 0.25, rna tf32)
    uint32_t qf[2][2][4];
    {
        const float* qbase = qkv + ((size_t)b * N_ + n0) * 384 + h * 16;
        #pragma unroll
        for (int i = 0; i < 2; i++)
            #pragma unroll
            for (int s = 0; s < 2; s++) {
                const float* p0 = qbase + (size_t)(16 * i + g) * 384 + 8 * s + tig;
                const float* p1 = p0 + 8 * 384;
                qf[i][s][0] = __float_as_uint(f2tf32(p0[0] * 0.25f));
                qf[i][s][1] = __float_as_uint(f2tf32(p1[0] * 0.25f));
                qf[i][s][2] = __float_as_uint(f2tf32(p0[4] * 0.25f));
                qf[i][s][3] = __float_as_uint(f2tf32(p1[4] * 0.25f));
            }
    }

    float oacc[2][2][4] = {};
    float lsum[4] = {0.f, 0.f, 0.f, 0.f};

    #pragma unroll 1
    for (int tile = 0; tile < 32; tile++) {
        int bi = tile & 1;
        if (tile < 31) cp_wait1(); else cp_wait0();
        __syncthreads();

        // ---- QK^T -------------------------------------------------------
        float sacc[2][4][4];
        #pragma unroll
        for (int i = 0; i < 2; i++)
            #pragma unroll
            for (int j = 0; j < 4; j++)
                #pragma unroll
                for (int e = 0; e < 4; e++) sacc[i][j][e] = 0.f;

        #pragma unroll
        for (int s = 0; s < 2; s++) {
            #pragma unroll
            for (int j = 0; j < 4; j++) {
                uint32_t bf[2];
                bf[0] = __float_as_uint(S.Ks[bi][8 * j + g][h * 16 + 8 * s + tig]);
                bf[1] = __float_as_uint(S.Ks[bi][8 * j + g][h * 16 + 8 * s + tig + 4]);
                mma_tf32(sacc[0][j], qf[0][s], bf);
                mma_tf32(sacc[1][j], qf[1][s], bf);
            }
        }

        // ---- epilogue: p = exp(s + w*invS); l += p; P -> smem (rna) -----
        #pragma unroll
        for (int i = 0; i < 2; i++) {
            float isA = i ? is2 : is0;
            float isB = i ? is3 : is1;
            #pragma unroll
            for (int j = 0; j < 4; j++) {
                int r0 = 16 * i + g;
                int c  = 8 * j + 2 * tig;
                float2 w0 = *(const float2*)&S.Wm[bi][r0][c];
                float2 w1 = *(const float2*)&S.Wm[bi][r0 + 8][c];
                float p0 = __expf(fmaf(w0.x, isA, sacc[i][j][0]));
                float p1 = __expf(fmaf(w0.y, isA, sacc[i][j][1]));
                float p2 = __expf(fmaf(w1.x, isB, sacc[i][j][2]));
                float p3 = __expf(fmaf(w1.y, isB, sacc[i][j][3]));
                lsum[2 * i]     += p0 + p1;
                lsum[2 * i + 1] += p2 + p3;
                *(float2*)&S.Ps[h][r0][c] =
                    make_float2(f2tf32(p0), f2tf32(p1));
                *(float2*)&S.Ps[h][r0 + 8][c] =
                    make_float2(f2tf32(p2), f2tf32(p3));
            }
        }
        __syncwarp();

        // ---- PV ----------------------------------------------------------
        #pragma unroll
        for (int kt = 0; kt < 4; kt++) {
            uint32_t bv[2][2];
            #pragma unroll
            for (int jd = 0; jd < 2; jd++) {
                bv[jd][0] = __float_as_uint(
                    S.Vs[bi][8 * kt + tig][h * 16 + 8 * jd + g]);
                bv[jd][1] = __float_as_uint(
                    S.Vs[bi][8 * kt + tig + 4][h * 16 + 8 * jd + g]);
            }
            uint32_t af[2][4];
            #pragma unroll
            for (int i = 0; i < 2; i++) {
                af[i][0] = __float_as_uint(S.Ps[h][16 * i + g][8 * kt + tig]);
                af[i][1] = __float_as_uint(S.Ps[h][16 * i + 8 + g][8 * kt + tig]);
                af[i][2] = __float_as_uint(S.Ps[h][16 * i + g][8 * kt + tig + 4]);
                af[i][3] = __float_as_uint(S.Ps[h][16 * i + 8 + g][8 * kt + tig + 4]);
            }
            #pragma unroll
            for (int i = 0; i < 2; i++)
                #pragma unroll
                for (int jd = 0; jd < 2; jd++)
                    mma_tf32(oacc[i][jd], af[i], bv[jd]);
        }

        __syncthreads();   // all reads of buf bi done
        if (tile + 2 < 32) {
            mha_issue(S, bi, kvbase, mbase, (tile + 2) * 32, t);
            cp_commit();
        }
    }

    // ---- finalize --------------------------------------------------------
    #pragma unroll
    for (int k = 0; k < 4; k++) {
        lsum[k] += __shfl_xor_sync(0xffffffffu, lsum[k], 1);
        lsum[k] += __shfl_xor_sync(0xffffffffu, lsum[k], 2);
    }
    #pragma unroll
    for (int i = 0; i < 2; i++) {
        float r0inv = 1.0f / lsum[2 * i];
        float r1inv = 1.0f / lsum[2 * i + 1];
        #pragma unroll
        for (int jd = 0; jd < 2; jd++) {
            size_t base0 = ((size_t)b * N_ + n0 + 16 * i + g) * 128
                           + h * 16 + 8 * jd + 2 * tig;
            size_t base1 = base0 + (size_t)8 * 128;
            *(float2*)&O[base0] = make_float2(oacc[i][jd][0] * r0inv,
                                              oacc[i][jd][1] * r0inv);
            *(float2*)&O[base1] = make_float2(oacc[i][jd][2] * r1inv,
                                              oacc[i][jd][3] * r1inv);
        }
    }
}

// ---------------------------------------------------------------------------
extern "C" void kernel_launch(void* const* d_in, const int* in_sizes, int n_in,
                              void* d_out, int out_size)
{
    const float* H     = (const float*)d_in[0];
    const float* A     = (const float*)d_in[1];
    const float* W_lin = (const float*)d_in[2];
    const float* b_lin = (const float*)d_in[3];
    const float* W_in  = (const float*)d_in[4];
    const float* b_in  = (const float*)d_in[5];
    const float* W_out = (const float*)d_in[6];
    const float* b_out = (const float*)d_in[7];
    const float* W_fin = (const float*)d_in[8];
    const float* b_fin = (const float*)d_in[9];
    float* out = (float*)d_out;

    float *Hp, *qkvp, *attnp, *rowsump, *op, *o2p;
    cudaGetSymbolAddress((void**)&Hp,      g_Hp);
    cudaGetSymbolAddress((void**)&qkvp,    g_qkv);
    cudaGetSymbolAddress((void**)&attnp,   g_attn);
    cudaGetSymbolAddress((void**)&rowsump, g_rowsum);
    cudaGetSymbolAddress((void**)&op,      g_o);
    cudaGetSymbolAddress((void**)&o2p,     g_o2);

    static int smem_set = 0;
    if (!smem_set) {
        cudaFuncSetAttribute(mha_tc, cudaFuncAttributeMaxDynamicSharedMemorySize,
                             (int)sizeof(MhaSmem));
        smem_set = 1;
    }

    // 1. Hp = H @ W_lin + b_lin               (8192 x 128)
    gemm_bias<<<dim3(128, 1), 256>>>(H, W_lin, b_lin, Hp, 128);
    // 2. qkv = Hp @ W_in + b_in               (8192 x 384)
    gemm_bias<<<dim3(128, 3), 256>>>(Hp, W_in, b_in, qkvp, 384);
    // 3. rowsum = 0
    cudaMemsetAsync(rowsump, 0, B_ * N_ * sizeof(float));
    // 4. tensor-core gated scores: e = exp(leaky(Hp Hp^T) * A), rowsum
    gated_tc<<<dim3(8, 16, 8), 256>>>(Hp, A, attnp, rowsump);
    // 5. tensor-core fused MHA (cp.async pipelined) -> o
    mha_tc<<<dim3(32, 8), 256, sizeof(MhaSmem)>>>(qkvp, attnp, rowsump, op);
    // 6. o2 = o @ W_out + b_out
    gemm_bias<<<dim3(128, 1), 256>>>(op, W_out, b_out, o2p, 128);
    // 7. out = o2 @ W_fin + b_fin
    gemm_bias<<<dim3(128, 1), 256>>>(o2p, W_fin, b_fin, out, 128);
}